// round 9
// baseline (speedup 1.0000x reference)
#include <cuda_runtime.h>
#include <math.h>

// Problem constants
#define NB   8
#define NT   2048
#define NJ   17
#define ND   129
#define NH   8
#define DH   16
#define NBJ  (NB * NJ)        // 136
#define NTOK (NBJ * NT)       // 278528
#define QKVN 384
#define TILE 128
#define PADA 132              // padded row stride for smem tiles (16B aligned)
#define KVSZ 272              // 16x16 kv + 16 ksum per (bj,h)

// Scratch (device globals: allocation-free rule)
__device__ float g_qkvm[(size_t)NTOK * QKVN];          // phi(q), phi(k), v per token
__device__ float g_kvtab[(size_t)NBJ * NH * KVSZ];     // per (bj,h): kv[16][16], ksum[16]

// ---------------- packed fp32x2 helpers (Blackwell FFMA2 path) ----------------
__device__ __forceinline__ unsigned long long pack_dup(float x) {
    unsigned long long r;
    asm("mov.b64 %0, {%1, %1};" : "=l"(r) : "f"(x));
    return r;
}
__device__ __forceinline__ void ffma2(unsigned long long& d, unsigned long long a,
                                      unsigned long long b) {
    asm("fma.rn.f32x2 %0, %1, %2, %0;" : "+l"(d) : "l"(a), "l"(b));
}
__device__ __forceinline__ float2 unpack2(unsigned long long v) {
    float2 f;
    asm("mov.b64 {%0, %1}, %2;" : "=f"(f.x), "=f"(f.y) : "l"(v));
    return f;
}

// Shared 128x128x128 micro-kernel: C[m0..+8][n0..+8] += As^T * Bs
// As, Bs are K-major: [k][m] / [k][n], row stride PADA.
__device__ __forceinline__ void gemm_tile_128(const float* __restrict__ As,
                                              const float* __restrict__ Bs,
                                              unsigned long long acc[8][4],
                                              int m0, int n0) {
#pragma unroll 4
    for (int k = 0; k < 128; k++) {
        const float4 a0 = *(const float4*)(As + k * PADA + m0);
        const float4 a1 = *(const float4*)(As + k * PADA + m0 + 4);
        const ulonglong2 b0 = *(const ulonglong2*)(Bs + k * PADA + n0);
        const ulonglong2 b1 = *(const ulonglong2*)(Bs + k * PADA + n0 + 4);
        unsigned long long bb[4] = {b0.x, b0.y, b1.x, b1.y};
        float av[8] = {a0.x, a0.y, a0.z, a0.w, a1.x, a1.y, a1.z, a1.w};
#pragma unroll
        for (int i = 0; i < 8; i++) {
            unsigned long long ad = pack_dup(av[i]);
#pragma unroll
            for (int u = 0; u < 4; u++) ffma2(acc[i][u], ad, bb[u]);
        }
    }
}

// ---------------------------------------------------------------------------
// Kernel 1: qkv = phi-epilogued GEMM.
// Grid: (NTOK/128, 3). blockIdx.y = s selects q/k/v 128-col slab of w_qkv.
// Each 128-token tile has a single (b, j) since 128 | T.
// ---------------------------------------------------------------------------
__global__ void __launch_bounds__(256, 1)
qkv_kernel(const float* __restrict__ x, const float* __restrict__ w_qkv,
           const float* __restrict__ b_qkv) {
    extern __shared__ float sm[];
    float* As = sm;                // [128][PADA]  x_spatial^T
    float* Bs = sm + TILE * PADA;  // [128][PADA]  w slab^T

    const int tile = blockIdx.x;
    const int s    = blockIdx.y;          // 0:q 1:k 2:v
    const int tid  = threadIdx.x;
    const int tok0 = tile * TILE;
    const int bj   = tok0 / NT;
    const int t0   = tok0 - bj * NT;
    const int b    = bj / NJ, j = bj - b * NJ;

    const float* xbase = x + ((size_t)(b * NT + t0) * NJ + j) * ND + 1;  // skip time col
    const size_t xstride = (size_t)NJ * ND;                               // 2193 floats

    const int lane = tid & 31;
    const int wp   = tid >> 5;
    // Load A tile (128 tokens x 128 spatial dims), transposed to K-major
    for (int r = wp; r < TILE; r += 8) {
        const float* xr = xbase + (size_t)r * xstride;
#pragma unroll
        for (int cc = 0; cc < 4; cc++) {
            int c = lane + 32 * cc;
            As[c * PADA + r] = __ldg(xr + c);
        }
    }
    // Load B slab (w_qkv rows s*128..s*128+127), transposed to K-major
    const float* wbase = w_qkv + (size_t)s * 128 * 128;
    for (int r = wp; r < 128; r += 8) {
        const float* wr = wbase + r * 128;
#pragma unroll
        for (int cc = 0; cc < 4; cc++) {
            int c = lane + 32 * cc;
            Bs[c * PADA + r] = __ldg(wr + c);
        }
    }
    __syncthreads();

    const int tm = tid >> 4, tn = tid & 15;
    const int m0 = tm * 8,  n0 = tn * 8;
    unsigned long long acc[8][4];
#pragma unroll
    for (int i = 0; i < 8; i++)
#pragma unroll
        for (int u = 0; u < 4; u++) acc[i][u] = 0ull;

    gemm_tile_128(As, Bs, acc, m0, n0);

    // Epilogue: +bias, phi (q,k slabs only), store to scratch
    float bias[8];
#pragma unroll
    for (int u = 0; u < 8; u++) bias[u] = __ldg(b_qkv + s * 128 + n0 + u);

#pragma unroll
    for (int i = 0; i < 8; i++) {
        float yv[8];
#pragma unroll
        for (int u = 0; u < 4; u++) {
            float2 p = unpack2(acc[i][u]);
            yv[2 * u]     = p.x + bias[2 * u];
            yv[2 * u + 1] = p.y + bias[2 * u + 1];
        }
        if (s < 2) {  // phi(x) = elu(x)+1
#pragma unroll
            for (int u = 0; u < 8; u++) {
                float v = yv[u];
                yv[u] = (v > 0.0f) ? (v + 1.0f) : expf(v);
            }
        }
        float* orow = g_qkvm + (size_t)(tok0 + m0 + i) * QKVN + s * 128 + n0;
        *(float4*)(orow)     = make_float4(yv[0], yv[1], yv[2], yv[3]);
        *(float4*)(orow + 4) = make_float4(yv[4], yv[5], yv[6], yv[7]);
    }
}

// ---------------------------------------------------------------------------
// Kernel 2: per (bj, h): kv[d][e] = sum_t k_m[t,d]*v[t,e], ksum[d] = sum_t k_m[t,d]
// Grid: NBJ*NH blocks, 256 threads; thread (i,e) owns kv[i][e].
// ---------------------------------------------------------------------------
__global__ void __launch_bounds__(256, 4)
kv_kernel() {
    const int bh = blockIdx.x;
    const int bj = bh >> 3, h = bh & 7;
    const int tid = threadIdx.x;
    const int i = tid >> 4, e = tid & 15;
    __shared__ float ks[16][16];
    __shared__ float vs[16][16];
    float kv = 0.0f, ksm = 0.0f;
    const size_t base = (size_t)bj * NT * QKVN + 128 + h * DH;  // k_m slab offset
    for (int tb = 0; tb < NT; tb += 16) {
#pragma unroll
        for (int r = 0; r < 2; r++) {
            int idx = tid + r * 256;
            int tt = idx >> 5;
            int which = (idx >> 4) & 1;  // 0 -> k_m, 1 -> v (offset +128)
            int li = idx & 15;
            float val = g_qkvm[base + (size_t)(tb + tt) * QKVN + which * 128 + li];
            if (which == 0) ks[tt][li] = val; else vs[tt][li] = val;
        }
        __syncthreads();
#pragma unroll
        for (int tt = 0; tt < 16; tt++) {
            float kk = ks[tt][i];
            kv = fmaf(kk, vs[tt][e], kv);
            if (e == 0) ksm += kk;
        }
        __syncthreads();
    }
    float* dst = g_kvtab + (size_t)bh * KVSZ;
    dst[i * 16 + e] = kv;
    if (e == 0) dst[256 + i] = ksm;
}

// ---------------------------------------------------------------------------
// Kernel 3: agg = (q_m @ kv) / clip(q_m . ksum, EPS), then y = agg @ w_out^T + b,
// y_time = sqrt(1 + |y|^2), write z = [y_time, y] at (B,T,J,D) layout.
// Grid: NTOK/128 blocks of 256 threads (one bj per block).
// ---------------------------------------------------------------------------
__global__ void __launch_bounds__(256, 1)
out_kernel(const float* __restrict__ w_out, const float* __restrict__ b_out,
           float* __restrict__ out) {
    extern __shared__ float sm[];
    float* Afs = sm;                     // [128][PADA] agg_flat^T (K-major)
    float* Ws  = sm + TILE * PADA;       // [128][PADA] w_out^T  (K-major)
    float* skv = sm + 2 * TILE * PADA;   // [NH*KVSZ]

    const int tile = blockIdx.x;
    const int tid  = threadIdx.x;
    const int tok0 = tile * TILE;
    const int bj   = tok0 / NT;
    const int t0   = tok0 - bj * NT;
    const int b    = bj / NJ, j = bj - b * NJ;

    const int lane = tid & 31, wp = tid >> 5;
    for (int r = wp; r < 128; r += 8) {
        const float* wr = w_out + r * 128;
#pragma unroll
        for (int cc = 0; cc < 4; cc++) {
            int c = lane + 32 * cc;
            Ws[c * PADA + r] = __ldg(wr + c);
        }
    }
    for (int idx = tid; idx < NH * KVSZ; idx += 256)
        skv[idx] = g_kvtab[(size_t)bj * NH * KVSZ + idx];
    __syncthreads();

    // Phase 1: agg_flat for 128 tokens (2 threads/token, 4 heads each)
    {
        const int m  = tid >> 1;
        const int hb = (tid & 1) * 4;
        const float* qrow = g_qkvm + (size_t)(tok0 + m) * QKVN;  // q_m at slab 0
#pragma unroll
        for (int hh = 0; hh < 4; hh++) {
            const int h = hb + hh;
            float q[16];
            const float4* q4 = (const float4*)(qrow + h * DH);
#pragma unroll
            for (int u = 0; u < 4; u++) {
                float4 t = q4[u];
                q[4 * u] = t.x; q[4 * u + 1] = t.y; q[4 * u + 2] = t.z; q[4 * u + 3] = t.w;
            }
            const float* kvh = skv + h * KVSZ;
            float a[16];
#pragma unroll
            for (int e = 0; e < 16; e++) a[e] = 0.0f;
            float denom = 0.0f;
#pragma unroll
            for (int i = 0; i < 16; i++) {
                const float qi = q[i];
                const float4* kr = (const float4*)(kvh + i * 16);
#pragma unroll
                for (int u = 0; u < 4; u++) {
                    float4 t = kr[u];
                    a[4 * u]     = fmaf(qi, t.x, a[4 * u]);
                    a[4 * u + 1] = fmaf(qi, t.y, a[4 * u + 1]);
                    a[4 * u + 2] = fmaf(qi, t.z, a[4 * u + 2]);
                    a[4 * u + 3] = fmaf(qi, t.w, a[4 * u + 3]);
                }
                denom = fmaf(qi, kvh[256 + i], denom);
            }
            denom = fmaxf(denom, 1e-6f);
            const float inv = 1.0f / denom;
#pragma unroll
            for (int e = 0; e < 16; e++)
                Afs[(h * DH + e) * PADA + m] = a[e] * inv;
        }
    }
    __syncthreads();

    // Phase 2: y = agg_flat @ w_out^T
    const int tm = tid >> 4, tn = tid & 15;
    const int m0 = tm * 8,  n0 = tn * 8;
    unsigned long long acc[8][4];
#pragma unroll
    for (int i = 0; i < 8; i++)
#pragma unroll
        for (int u = 0; u < 4; u++) acc[i][u] = 0ull;

    gemm_tile_128(Afs, Ws, acc, m0, n0);

    float bias[8];
#pragma unroll
    for (int u = 0; u < 8; u++) bias[u] = __ldg(b_out + n0 + u);

    // Epilogue: bias, per-token |y|^2 via half-warp shfl (16 threads own a row),
    // y_time, scatter to (B,T,J,129) layout.
#pragma unroll
    for (int i = 0; i < 8; i++) {
        float yv[8];
#pragma unroll
        for (int u = 0; u < 4; u++) {
            float2 p = unpack2(acc[i][u]);
            yv[2 * u]     = p.x + bias[2 * u];
            yv[2 * u + 1] = p.y + bias[2 * u + 1];
        }
        float p = 0.0f;
#pragma unroll
        for (int u = 0; u < 8; u++) p = fmaf(yv[u], yv[u], p);
        p += __shfl_xor_sync(0xffffffffu, p, 1);
        p += __shfl_xor_sync(0xffffffffu, p, 2);
        p += __shfl_xor_sync(0xffffffffu, p, 4);
        p += __shfl_xor_sync(0xffffffffu, p, 8);

        const int t = t0 + m0 + i;
        float* orow = out + ((size_t)(b * NT + t) * NJ + j) * ND;
        if (tn == 0) orow[0] = sqrtf(1.0f + p);
#pragma unroll
        for (int u = 0; u < 8; u++) orow[1 + n0 + u] = yv[u];
    }
}

// ---------------------------------------------------------------------------
extern "C" void kernel_launch(void* const* d_in, const int* in_sizes, int n_in,
                              void* d_out, int out_size) {
    (void)in_sizes; (void)n_in; (void)out_size;
    const float* x     = (const float*)d_in[0];
    const float* w_qkv = (const float*)d_in[1];
    const float* b_qkv = (const float*)d_in[2];
    const float* w_out = (const float*)d_in[3];
    const float* b_out = (const float*)d_in[4];
    float* out = (float*)d_out;

    const int smem1 = 2 * TILE * PADA * 4;                    // 135168 B
    const int smem3 = (2 * TILE * PADA + NH * KVSZ) * 4;      // 143872 B
    cudaFuncSetAttribute(qkv_kernel, cudaFuncAttributeMaxDynamicSharedMemorySize, smem1);
    cudaFuncSetAttribute(out_kernel, cudaFuncAttributeMaxDynamicSharedMemorySize, smem3);

    qkv_kernel<<<dim3(NTOK / TILE, 3), 256, smem1>>>(x, w_qkv, b_qkv);
    kv_kernel<<<NBJ * NH, 256>>>();
    out_kernel<<<NTOK / TILE, 256, smem3>>>(w_out, b_out, out);
}

// round 10
// speedup vs baseline: 1.0006x; 1.0006x over previous
#include <cuda_runtime.h>
#include <math.h>

// Problem constants
#define NB   8
#define NT   2048
#define NJ   17
#define ND   129
#define NH   8
#define DH   16
#define NBJ  (NB * NJ)        // 136
#define NTOK (NBJ * NT)       // 278528
#define QKVN 384
#define TILE 128
#define PADA 132              // padded row stride for smem tiles (16B aligned)
#define KVSZ 272              // 16x16 kv + 16 ksum per (bj,h)

// Scratch (device globals: allocation-free rule)
__device__ float g_qkvm[(size_t)NTOK * QKVN];          // phi(q), phi(k), v per token
__device__ float g_kvtab[(size_t)NBJ * NH * KVSZ];     // per (bj,h): kv[16][16], ksum[16]

// ---------------- packed fp32x2 helpers (Blackwell FFMA2 path) ----------------
__device__ __forceinline__ unsigned long long pack_dup(float x) {
    unsigned long long r;
    asm("mov.b64 %0, {%1, %1};" : "=l"(r) : "f"(x));
    return r;
}
__device__ __forceinline__ void ffma2(unsigned long long& d, unsigned long long a,
                                      unsigned long long b) {
    asm("fma.rn.f32x2 %0, %1, %2, %0;" : "+l"(d) : "l"(a), "l"(b));
}
__device__ __forceinline__ float2 unpack2(unsigned long long v) {
    float2 f;
    asm("mov.b64 {%0, %1}, %2;" : "=f"(f.x), "=f"(f.y) : "l"(v));
    return f;
}

// Shared 128x128x128 micro-kernel: C[m0..+8][n0..+8] += As^T * Bs
// As, Bs are K-major: [k][m] / [k][n], row stride PADA.
__device__ __forceinline__ void gemm_tile_128(const float* __restrict__ As,
                                              const float* __restrict__ Bs,
                                              unsigned long long acc[8][4],
                                              int m0, int n0) {
#pragma unroll 4
    for (int k = 0; k < 128; k++) {
        const float4 a0 = *(const float4*)(As + k * PADA + m0);
        const float4 a1 = *(const float4*)(As + k * PADA + m0 + 4);
        const ulonglong2 b0 = *(const ulonglong2*)(Bs + k * PADA + n0);
        const ulonglong2 b1 = *(const ulonglong2*)(Bs + k * PADA + n0 + 4);
        unsigned long long bb[4] = {b0.x, b0.y, b1.x, b1.y};
        float av[8] = {a0.x, a0.y, a0.z, a0.w, a1.x, a1.y, a1.z, a1.w};
#pragma unroll
        for (int i = 0; i < 8; i++) {
            unsigned long long ad = pack_dup(av[i]);
#pragma unroll
            for (int u = 0; u < 4; u++) ffma2(acc[i][u], ad, bb[u]);
        }
    }
}

// ---------------------------------------------------------------------------
// Kernel 1: qkv = phi-epilogued GEMM.
// Grid: (NTOK/128, 3). blockIdx.y = s selects q/k/v 128-col slab of w_qkv.
// Each 128-token tile has a single (b, j) since 128 | T.
// ---------------------------------------------------------------------------
__global__ void __launch_bounds__(256, 1)
qkv_kernel(const float* __restrict__ x, const float* __restrict__ w_qkv,
           const float* __restrict__ b_qkv) {
    extern __shared__ float sm[];
    float* As = sm;                // [128][PADA]  x_spatial^T
    float* Bs = sm + TILE * PADA;  // [128][PADA]  w slab^T

    const int tile = blockIdx.x;
    const int s    = blockIdx.y;          // 0:q 1:k 2:v
    const int tid  = threadIdx.x;
    const int tok0 = tile * TILE;
    const int bj   = tok0 / NT;
    const int t0   = tok0 - bj * NT;
    const int b    = bj / NJ, j = bj - b * NJ;

    const float* xbase = x + ((size_t)(b * NT + t0) * NJ + j) * ND + 1;  // skip time col
    const size_t xstride = (size_t)NJ * ND;                               // 2193 floats

    const int lane = tid & 31;
    const int wp   = tid >> 5;
    // Load A tile (128 tokens x 128 spatial dims), transposed to K-major
    for (int r = wp; r < TILE; r += 8) {
        const float* xr = xbase + (size_t)r * xstride;
#pragma unroll
        for (int cc = 0; cc < 4; cc++) {
            int c = lane + 32 * cc;
            As[c * PADA + r] = __ldg(xr + c);
        }
    }
    // Load B slab (w_qkv rows s*128..s*128+127), transposed to K-major
    const float* wbase = w_qkv + (size_t)s * 128 * 128;
    for (int r = wp; r < 128; r += 8) {
        const float* wr = wbase + r * 128;
#pragma unroll
        for (int cc = 0; cc < 4; cc++) {
            int c = lane + 32 * cc;
            Bs[c * PADA + r] = __ldg(wr + c);
        }
    }
    __syncthreads();

    const int tm = tid >> 4, tn = tid & 15;
    const int m0 = tm * 8,  n0 = tn * 8;
    unsigned long long acc[8][4];
#pragma unroll
    for (int i = 0; i < 8; i++)
#pragma unroll
        for (int u = 0; u < 4; u++) acc[i][u] = 0ull;

    gemm_tile_128(As, Bs, acc, m0, n0);

    // Epilogue: +bias, phi (q,k slabs only), store to scratch
    float bias[8];
#pragma unroll
    for (int u = 0; u < 8; u++) bias[u] = __ldg(b_qkv + s * 128 + n0 + u);

#pragma unroll
    for (int i = 0; i < 8; i++) {
        float yv[8];
#pragma unroll
        for (int u = 0; u < 4; u++) {
            float2 p = unpack2(acc[i][u]);
            yv[2 * u]     = p.x + bias[2 * u];
            yv[2 * u + 1] = p.y + bias[2 * u + 1];
        }
        if (s < 2) {  // phi(x) = elu(x)+1
#pragma unroll
            for (int u = 0; u < 8; u++) {
                float v = yv[u];
                yv[u] = (v > 0.0f) ? (v + 1.0f) : expf(v);
            }
        }
        float* orow = g_qkvm + (size_t)(tok0 + m0 + i) * QKVN + s * 128 + n0;
        *(float4*)(orow)     = make_float4(yv[0], yv[1], yv[2], yv[3]);
        *(float4*)(orow + 4) = make_float4(yv[4], yv[5], yv[6], yv[7]);
    }
}

// ---------------------------------------------------------------------------
// Kernel 2: per (bj, h): kv[d][e] = sum_t k_m[t,d]*v[t,e], ksum[d] = sum_t k_m[t,d]
// Grid: NBJ*NH blocks, 256 threads; thread (i,e) owns kv[i][e].
// ---------------------------------------------------------------------------
__global__ void __launch_bounds__(256, 4)
kv_kernel() {
    const int bh = blockIdx.x;
    const int bj = bh >> 3, h = bh & 7;
    const int tid = threadIdx.x;
    const int i = tid >> 4, e = tid & 15;
    __shared__ float ks[16][16];
    __shared__ float vs[16][16];
    float kv = 0.0f, ksm = 0.0f;
    const size_t base = (size_t)bj * NT * QKVN + 128 + h * DH;  // k_m slab offset
    for (int tb = 0; tb < NT; tb += 16) {
#pragma unroll
        for (int r = 0; r < 2; r++) {
            int idx = tid + r * 256;
            int tt = idx >> 5;
            int which = (idx >> 4) & 1;  // 0 -> k_m, 1 -> v (offset +128)
            int li = idx & 15;
            float val = g_qkvm[base + (size_t)(tb + tt) * QKVN + which * 128 + li];
            if (which == 0) ks[tt][li] = val; else vs[tt][li] = val;
        }
        __syncthreads();
#pragma unroll
        for (int tt = 0; tt < 16; tt++) {
            float kk = ks[tt][i];
            kv = fmaf(kk, vs[tt][e], kv);
            if (e == 0) ksm += kk;
        }
        __syncthreads();
    }
    float* dst = g_kvtab + (size_t)bh * KVSZ;
    dst[i * 16 + e] = kv;
    if (e == 0) dst[256 + i] = ksm;
}

// ---------------------------------------------------------------------------
// Kernel 3: agg = (q_m @ kv) / clip(q_m . ksum, EPS), then y = agg @ w_out^T + b,
// y_time = sqrt(1 + |y|^2), write z = [y_time, y] at (B,T,J,D) layout.
// Grid: NTOK/128 blocks of 256 threads (one bj per block).
// ---------------------------------------------------------------------------
__global__ void __launch_bounds__(256, 1)
out_kernel(const float* __restrict__ w_out, const float* __restrict__ b_out,
           float* __restrict__ out) {
    extern __shared__ float sm[];
    float* Afs = sm;                     // [128][PADA] agg_flat^T (K-major)
    float* Ws  = sm + TILE * PADA;       // [128][PADA] w_out^T  (K-major)
    float* skv = sm + 2 * TILE * PADA;   // [NH*KVSZ]

    const int tile = blockIdx.x;
    const int tid  = threadIdx.x;
    const int tok0 = tile * TILE;
    const int bj   = tok0 / NT;
    const int t0   = tok0 - bj * NT;
    const int b    = bj / NJ, j = bj - b * NJ;

    const int lane = tid & 31, wp = tid >> 5;
    for (int r = wp; r < 128; r += 8) {
        const float* wr = w_out + r * 128;
#pragma unroll
        for (int cc = 0; cc < 4; cc++) {
            int c = lane + 32 * cc;
            Ws[c * PADA + r] = __ldg(wr + c);
        }
    }
    for (int idx = tid; idx < NH * KVSZ; idx += 256)
        skv[idx] = g_kvtab[(size_t)bj * NH * KVSZ + idx];
    __syncthreads();

    // Phase 1: agg_flat for 128 tokens (2 threads/token, 4 heads each)
    {
        const int m  = tid >> 1;
        const int hb = (tid & 1) * 4;
        const float* qrow = g_qkvm + (size_t)(tok0 + m) * QKVN;  // q_m at slab 0
#pragma unroll
        for (int hh = 0; hh < 4; hh++) {
            const int h = hb + hh;
            float q[16];
            const float4* q4 = (const float4*)(qrow + h * DH);
#pragma unroll
            for (int u = 0; u < 4; u++) {
                float4 t = q4[u];
                q[4 * u] = t.x; q[4 * u + 1] = t.y; q[4 * u + 2] = t.z; q[4 * u + 3] = t.w;
            }
            const float* kvh = skv + h * KVSZ;
            float a[16];
#pragma unroll
            for (int e = 0; e < 16; e++) a[e] = 0.0f;
            float denom = 0.0f;
#pragma unroll
            for (int i = 0; i < 16; i++) {
                const float qi = q[i];
                const float4* kr = (const float4*)(kvh + i * 16);
#pragma unroll
                for (int u = 0; u < 4; u++) {
                    float4 t = kr[u];
                    a[4 * u]     = fmaf(qi, t.x, a[4 * u]);
                    a[4 * u + 1] = fmaf(qi, t.y, a[4 * u + 1]);
                    a[4 * u + 2] = fmaf(qi, t.z, a[4 * u + 2]);
                    a[4 * u + 3] = fmaf(qi, t.w, a[4 * u + 3]);
                }
                denom = fmaf(qi, kvh[256 + i], denom);
            }
            denom = fmaxf(denom, 1e-6f);
            const float inv = 1.0f / denom;
#pragma unroll
            for (int e = 0; e < 16; e++)
                Afs[(h * DH + e) * PADA + m] = a[e] * inv;
        }
    }
    __syncthreads();

    // Phase 2: y = agg_flat @ w_out^T
    const int tm = tid >> 4, tn = tid & 15;
    const int m0 = tm * 8,  n0 = tn * 8;
    unsigned long long acc[8][4];
#pragma unroll
    for (int i = 0; i < 8; i++)
#pragma unroll
        for (int u = 0; u < 4; u++) acc[i][u] = 0ull;

    gemm_tile_128(Afs, Ws, acc, m0, n0);

    float bias[8];
#pragma unroll
    for (int u = 0; u < 8; u++) bias[u] = __ldg(b_out + n0 + u);

    // Epilogue: bias, per-token |y|^2 via half-warp shfl (16 threads own a row),
    // y_time, scatter to (B,T,J,129) layout.
#pragma unroll
    for (int i = 0; i < 8; i++) {
        float yv[8];
#pragma unroll
        for (int u = 0; u < 4; u++) {
            float2 p = unpack2(acc[i][u]);
            yv[2 * u]     = p.x + bias[2 * u];
            yv[2 * u + 1] = p.y + bias[2 * u + 1];
        }
        float p = 0.0f;
#pragma unroll
        for (int u = 0; u < 8; u++) p = fmaf(yv[u], yv[u], p);
        p += __shfl_xor_sync(0xffffffffu, p, 1);
        p += __shfl_xor_sync(0xffffffffu, p, 2);
        p += __shfl_xor_sync(0xffffffffu, p, 4);
        p += __shfl_xor_sync(0xffffffffu, p, 8);

        const int t = t0 + m0 + i;
        float* orow = out + ((size_t)(b * NT + t) * NJ + j) * ND;
        if (tn == 0) orow[0] = sqrtf(1.0f + p);
#pragma unroll
        for (int u = 0; u < 8; u++) orow[1 + n0 + u] = yv[u];
    }
}

// ---------------------------------------------------------------------------
extern "C" void kernel_launch(void* const* d_in, const int* in_sizes, int n_in,
                              void* d_out, int out_size) {
    (void)in_sizes; (void)n_in; (void)out_size;
    const float* x     = (const float*)d_in[0];
    const float* w_qkv = (const float*)d_in[1];
    const float* b_qkv = (const float*)d_in[2];
    const float* w_out = (const float*)d_in[3];
    const float* b_out = (const float*)d_in[4];
    float* out = (float*)d_out;

    const int smem1 = 2 * TILE * PADA * 4;                    // 135168 B
    const int smem3 = (2 * TILE * PADA + NH * KVSZ) * 4;      // 143872 B
    cudaFuncSetAttribute(qkv_kernel, cudaFuncAttributeMaxDynamicSharedMemorySize, smem1);
    cudaFuncSetAttribute(out_kernel, cudaFuncAttributeMaxDynamicSharedMemorySize, smem3);

    qkv_kernel<<<dim3(NTOK / TILE, 3), 256, smem1>>>(x, w_qkv, b_qkv);
    kv_kernel<<<NBJ * NH, 256>>>();
    out_kernel<<<NTOK / TILE, 256, smem3>>>(w_out, b_out, out);
}